// round 1
// baseline (speedup 1.0000x reference)
#include <cuda_runtime.h>
#include <cstdint>

#define N_NODES 10000
#define N_EDGES_MAX 320000
#define BB 4
#define TT 12
#define FINF 2
#define HID 64
#define OUTD 16
#define NB (N_NODES*BB)        /* 40000 rows (n,b) */
#define NC (BB*FINF*TT)        /* 96 features per node */
#define TILE_R 256
#define PAD 65

// ---------------- device scratch (no allocations allowed) ----------------
__device__ float g_deg[N_NODES];
__device__ float g_dinv[N_NODES];
__device__ int   g_count[N_NODES];
__device__ int   g_rowptr[N_NODES + 1];
__device__ int   g_cursor[N_NODES];
__device__ int   g_csrc[N_EDGES_MAX];
__device__ float g_cw[N_EDGES_MAX];
__device__ float g_xT[N_NODES * NC];
__device__ float g_ax[N_NODES * NC];
__device__ float g_H[2][NB * HID];
__device__ float g_M[384];    // folded x-path: [gate(3)][fin(2)][64]
__device__ float g_gb[192];   // folded gate bias: [gate(3)][64]

// ---------------- init: zero H0, deg=1 (self loop), count=0 ----------------
__global__ void k_init() {
    int i = blockIdx.x * blockDim.x + threadIdx.x;
    if (i < NB * HID) g_H[0][i] = 0.f;
    if (i < N_NODES) { g_deg[i] = 1.0f; g_count[i] = 0; }
}

// ---------------- transpose x [B,N,F,T] -> xT [N][ (b*2+f)*12+t ] ----------------
__global__ void k_xT(const float* __restrict__ x) {
    int i = blockIdx.x * blockDim.x + threadIdx.x;
    if (i >= N_NODES * NC) return;
    int n = i / NC, c = i % NC;
    int b = c / (FINF * TT);
    int rem = c % (FINF * TT);
    int f = rem / TT, t = rem % TT;
    g_xT[i] = x[(((size_t)b * N_NODES + n) * FINF + f) * TT + t];
}

// ---------------- per-edge degree + count ----------------
__global__ void k_edge(const int* __restrict__ ei, const float* __restrict__ ew, int E) {
    int e = blockIdx.x * blockDim.x + threadIdx.x;
    if (e >= E) return;
    int d = ei[E + e];
    atomicAdd(&g_deg[d], ew[e]);
    atomicAdd(&g_count[d], 1);
}

__global__ void k_dinv() {
    int n = blockIdx.x * blockDim.x + threadIdx.x;
    if (n < N_NODES) g_dinv[n] = rsqrtf(g_deg[n]);  // deg >= 1 always (self loop)
}

// ---------------- single-block exclusive scan of counts -> rowptr, cursor ----------------
__global__ void k_scan() {
    __shared__ int sums[1024];
    const int CH = 10;  // 1024*10 >= 10001
    int tid = threadIdx.x;
    int base = tid * CH;
    int local[CH];
    int s = 0;
    for (int j = 0; j < CH; j++) {
        int idx = base + j;
        int v = (idx < N_NODES) ? g_count[idx] : 0;
        local[j] = s;
        s += v;
    }
    sums[tid] = s;
    __syncthreads();
    for (int off = 1; off < 1024; off <<= 1) {
        int v = (tid >= off) ? sums[tid - off] : 0;
        __syncthreads();
        sums[tid] += v;
        __syncthreads();
    }
    int offset = (tid > 0) ? sums[tid - 1] : 0;
    for (int j = 0; j < CH; j++) {
        int idx = base + j;
        if (idx <= N_NODES) {
            int v = offset + local[j];
            g_rowptr[idx] = v;
            if (idx < N_NODES) g_cursor[idx] = v;
        }
    }
}

// ---------------- scatter edges into CSR with normalized weight ----------------
__global__ void k_scatter(const int* __restrict__ ei, const float* __restrict__ ew, int E) {
    int e = blockIdx.x * blockDim.x + threadIdx.x;
    if (e >= E) return;
    int s = ei[e];
    int d = ei[E + e];
    int pos = atomicAdd(&g_cursor[d], 1);
    g_csrc[pos] = s;
    g_cw[pos] = g_dinv[s] * ew[e] * g_dinv[d];
}

// ---------------- aggregate: ax[n] = sum_in norm * xT[src] + dinv^2 * xT[n] ----------------
__global__ void k_agg() {
    int warp = (blockIdx.x * blockDim.x + threadIdx.x) >> 5;
    int lane = threadIdx.x & 31;
    if (warp >= N_NODES) return;
    int n = warp;
    float dv = g_dinv[n];
    float self_w = dv * dv;
    float a0 = self_w * g_xT[(size_t)n * NC + lane];
    float a1 = self_w * g_xT[(size_t)n * NC + lane + 32];
    float a2 = self_w * g_xT[(size_t)n * NC + lane + 64];
    int e0 = g_rowptr[n], e1 = g_rowptr[n + 1];
    for (int e = e0; e < e1; e++) {
        int s = g_csrc[e];
        float w = g_cw[e];
        const float* xs = &g_xT[(size_t)s * NC];
        a0 += w * xs[lane];
        a1 += w * xs[lane + 32];
        a2 += w * xs[lane + 64];
    }
    g_ax[(size_t)n * NC + lane] = a0;
    g_ax[(size_t)n * NC + lane + 32] = a1;
    g_ax[(size_t)n * NC + lane + 64] = a2;
}

// ---------------- fold x-path matrices: M = W @ L_top, gb = b @ L_top + L_b ----------------
__global__ void k_fold(const float* __restrict__ Wz, const float* __restrict__ bz,
                       const float* __restrict__ Wr, const float* __restrict__ br,
                       const float* __restrict__ Wh, const float* __restrict__ bh,
                       const float* __restrict__ Lz, const float* __restrict__ Lzb,
                       const float* __restrict__ Lr, const float* __restrict__ Lrb,
                       const float* __restrict__ Lh, const float* __restrict__ Lhb) {
    int tid = threadIdx.x;  // 0..191
    if (tid >= 192) return;
    int g = tid >> 6, j = tid & 63;
    const float* W  = (g == 0) ? Wz  : (g == 1) ? Wr  : Wh;
    const float* bv = (g == 0) ? bz  : (g == 1) ? br  : bh;
    const float* L  = (g == 0) ? Lz  : (g == 1) ? Lr  : Lh;
    const float* Lb = (g == 0) ? Lzb : (g == 1) ? Lrb : Lhb;
    float m0 = 0.f, m1 = 0.f, gbv = 0.f;
    for (int m = 0; m < 64; m++) {
        float l = L[m * 64 + j];
        m0 += W[m] * l;
        m1 += W[64 + m] * l;
        gbv += bv[m] * l;
    }
    g_M[g * 128 + j] = m0;
    g_M[g * 128 + 64 + j] = m1;
    g_gb[g * 64 + j] = gbv + Lb[j];
}

// ---------------- fused GRU step: gates, candidate, state update, output ----------------
// smem layout (floats):
//   sH  [256][65]   H tile
//   sHr [256][65]   H*R tile, later relu(Hn)
//   sW1 [64][128]   [Lz_bot | Lr_bot]
//   sW2 [64][64]    Lh_bot
//   sLin[64][16]
//   sM  [384], sGb [192], sLb [16]
#define SMEM_FLOATS (2*TILE_R*PAD + 64*128 + 64*64 + 64*16 + 384 + 192 + 16)

__global__ __launch_bounds__(512, 1)
void k_step(const float* __restrict__ Lz, const float* __restrict__ Lr,
            const float* __restrict__ Lh, const float* __restrict__ lw,
            const float* __restrict__ lb, float* __restrict__ out, int t) {
    extern __shared__ float sm[];
    float* sH   = sm;
    float* sHr  = sH + TILE_R * PAD;
    float* sW1  = sHr + TILE_R * PAD;
    float* sW2  = sW1 + 64 * 128;
    float* sLin = sW2 + 64 * 64;
    float* sM   = sLin + 64 * 16;
    float* sGb  = sM + 384;
    float* sLb  = sGb + 192;

    const float* Hin = g_H[t & 1];
    float* Hout = g_H[(t + 1) & 1];

    int tid = threadIdx.x;
    int row0 = blockIdx.x * TILE_R;

    // load weights
    for (int i = tid; i < 64 * 128; i += 512) {
        int k = i >> 7, j = i & 127;
        sW1[i] = (j < 64) ? Lz[(64 + k) * 64 + j] : Lr[(64 + k) * 64 + (j - 64)];
    }
    for (int i = tid; i < 64 * 64; i += 512) {
        int k = i >> 6, j = i & 63;
        sW2[i] = Lh[(64 + k) * 64 + j];
    }
    for (int i = tid; i < 64 * 16; i += 512) sLin[i] = lw[i];
    for (int i = tid; i < 384; i += 512) sM[i] = g_M[i];
    for (int i = tid; i < 192; i += 512) sGb[i] = g_gb[i];
    if (tid < 16) sLb[tid] = lb[tid];

    // load H tile
    for (int i = tid; i < TILE_R * 64; i += 512) {
        int r = i >> 6, k = i & 63;
        int row = row0 + r;
        sH[r * PAD + k] = (row < NB) ? Hin[(size_t)row * 64 + k] : 0.f;
    }
    __syncthreads();

    int tx = tid & 15;   // col group: cols tx*4..tx*4+3 (per gate)
    int ty = tid >> 4;   // row group: rows ty*8..ty*8+7
    int rbase = ty * 8;
    int cz = tx * 4;

    // x-path inputs for this thread's rows
    float ax0[8], ax1[8];
#pragma unroll
    for (int i = 0; i < 8; i++) {
        int row = row0 + rbase + i;
        if (row < NB) {
            int n = row >> 2, b = row & 3;
            ax0[i] = g_ax[(size_t)n * NC + (b * 2 + 0) * TT + t];
            ax1[i] = g_ax[(size_t)n * NC + (b * 2 + 1) * TT + t];
        } else { ax0[i] = 0.f; ax1[i] = 0.f; }
    }

    // ---- GEMM1: gate preactivations (z: cols cz.., r: cols 64+cz..) ----
    float accZ[8][4], accR[8][4];
#pragma unroll
    for (int i = 0; i < 8; i++)
#pragma unroll
        for (int c = 0; c < 4; c++) {
            int j = cz + c;
            accZ[i][c] = sGb[j]      + ax0[i] * sM[j]       + ax1[i] * sM[64 + j];
            accR[i][c] = sGb[64 + j] + ax0[i] * sM[128 + j] + ax1[i] * sM[192 + j];
        }
    for (int k = 0; k < 64; k++) {
        float a[8];
#pragma unroll
        for (int i = 0; i < 8; i++) a[i] = sH[(rbase + i) * PAD + k];
        float bz4[4], br4[4];
#pragma unroll
        for (int c = 0; c < 4; c++) {
            bz4[c] = sW1[k * 128 + cz + c];
            br4[c] = sW1[k * 128 + 64 + cz + c];
        }
#pragma unroll
        for (int i = 0; i < 8; i++)
#pragma unroll
            for (int c = 0; c < 4; c++) {
                accZ[i][c] += a[i] * bz4[c];
                accR[i][c] += a[i] * br4[c];
            }
    }

    // Z = sigmoid, R = sigmoid; write Hr = H .* R
    float Z[8][4];
#pragma unroll
    for (int i = 0; i < 8; i++)
#pragma unroll
        for (int c = 0; c < 4; c++) {
            Z[i][c] = 1.f / (1.f + __expf(-accZ[i][c]));
            float R = 1.f / (1.f + __expf(-accR[i][c]));
            int idx = (rbase + i) * PAD + cz + c;
            sHr[idx] = sH[idx] * R;
        }
    __syncthreads();

    // ---- GEMM2: candidate preactivation ----
    float accH[8][4];
#pragma unroll
    for (int i = 0; i < 8; i++)
#pragma unroll
        for (int c = 0; c < 4; c++) {
            int j = cz + c;
            accH[i][c] = sGb[128 + j] + ax0[i] * sM[256 + j] + ax1[i] * sM[320 + j];
        }
    for (int k = 0; k < 64; k++) {
        float a[8];
#pragma unroll
        for (int i = 0; i < 8; i++) a[i] = sHr[(rbase + i) * PAD + k];
        float b4[4];
#pragma unroll
        for (int c = 0; c < 4; c++) b4[c] = sW2[k * 64 + cz + c];
#pragma unroll
        for (int i = 0; i < 8; i++)
#pragma unroll
            for (int c = 0; c < 4; c++) accH[i][c] += a[i] * b4[c];
    }
    __syncthreads();  // all GEMM2 reads of sHr done before overwrite

    // Hn = Z*H + (1-Z)*tanh(accH); write Hout; relu(Hn) -> sHr
#pragma unroll
    for (int i = 0; i < 8; i++) {
        int row = row0 + rbase + i;
#pragma unroll
        for (int c = 0; c < 4; c++) {
            float ht = tanhf(accH[i][c]);
            int idx = (rbase + i) * PAD + cz + c;
            float h = sH[idx];
            float z = Z[i][c];
            float hn = z * h + (1.f - z) * ht;
            if (row < NB) Hout[(size_t)row * 64 + cz + c] = hn;
            sHr[idx] = fmaxf(hn, 0.f);
        }
    }
    __syncthreads();

    // ---- GEMM3: out = relu(Hn) @ lin_w + lin_b ----
    int r3 = tid >> 1;              // 0..255
    int o0 = (tid & 1) * 8;         // 0 or 8
    float acc[8];
#pragma unroll
    for (int j = 0; j < 8; j++) acc[j] = sLb[o0 + j];
    for (int k = 0; k < 64; k++) {
        float a = sHr[r3 * PAD + k];
#pragma unroll
        for (int j = 0; j < 8; j++) acc[j] += a * sLin[k * 16 + o0 + j];
    }
    int row = row0 + r3;
    if (row < NB) {
        int n = row >> 2, b = row & 3;
        float* op = out + ((((size_t)b * TT + t) * N_NODES + n) * OUTD + o0);
#pragma unroll
        for (int j = 0; j < 8; j++) op[j] = acc[j];
    }
}

// ---------------- launch ----------------
extern "C" void kernel_launch(void* const* d_in, const int* in_sizes, int n_in,
                              void* d_out, int out_size) {
    const float* x   = (const float*)d_in[0];
    const int*   ei  = (const int*)d_in[1];
    const float* ew  = (const float*)d_in[2];
    const float* Wz  = (const float*)d_in[3];
    const float* bz  = (const float*)d_in[4];
    const float* Wr  = (const float*)d_in[5];
    const float* br  = (const float*)d_in[6];
    const float* Wh  = (const float*)d_in[7];
    const float* bh  = (const float*)d_in[8];
    const float* Lz  = (const float*)d_in[9];
    const float* Lzb = (const float*)d_in[10];
    const float* Lr  = (const float*)d_in[11];
    const float* Lrb = (const float*)d_in[12];
    const float* Lh  = (const float*)d_in[13];
    const float* Lhb = (const float*)d_in[14];
    const float* lw  = (const float*)d_in[15];
    const float* lb  = (const float*)d_in[16];
    float* out = (float*)d_out;

    int E = in_sizes[2];
    if (E > N_EDGES_MAX) E = N_EDGES_MAX;

    const int smem_bytes = SMEM_FLOATS * (int)sizeof(float);
    cudaFuncSetAttribute(k_step, cudaFuncAttributeMaxDynamicSharedMemorySize, smem_bytes);

    k_init<<<(NB * HID + 255) / 256, 256>>>();
    k_xT<<<(N_NODES * NC + 255) / 256, 256>>>(x);
    k_edge<<<(E + 255) / 256, 256>>>(ei, ew, E);
    k_dinv<<<(N_NODES + 255) / 256, 256>>>();
    k_scan<<<1, 1024>>>();
    k_scatter<<<(E + 255) / 256, 256>>>(ei, ew, E);
    k_agg<<<(N_NODES + 7) / 8, 256>>>();
    k_fold<<<1, 192>>>(Wz, bz, Wr, br, Wh, bh, Lz, Lzb, Lr, Lrb, Lh, Lhb);

    int grid = (NB + TILE_R - 1) / TILE_R;  // 157
    for (int t = 0; t < TT; t++) {
        k_step<<<grid, 512, smem_bytes>>>(Lz, Lr, Lh, lw, lb, out, t);
    }
}

// round 2
// speedup vs baseline: 1.5183x; 1.5183x over previous
#include <cuda_runtime.h>
#include <cstdint>

#define N_NODES 10000
#define N_EDGES_MAX 320000
#define BB 4
#define TT 12
#define FINF 2
#define HID 64
#define OUTD 16
#define NB (N_NODES*BB)        /* 40000 rows (n,b) */
#define NC (BB*FINF*TT)        /* 96 features per node */

#define TILE_R 264             /* rows per block: ceil(40000/264)=152 blocks = 1 full wave */
#define NTHREADS 544           /* 17 warps: 33 ty * 16 tx compute threads (528) + 16 idle */
#define TY_COMPUTE 33
#define LDT 266                /* transposed H tile leading dim (even for LDS.64, odd/32 spread) */

// ---------------- device scratch (no allocations allowed) ----------------
__device__ float g_deg[N_NODES];
__device__ float g_dinv[N_NODES];
__device__ int   g_count[N_NODES];
__device__ int   g_rowptr[N_NODES + 1];
__device__ int   g_cursor[N_NODES];
__device__ int   g_csrc[N_EDGES_MAX];
__device__ float g_cw[N_EDGES_MAX];
__device__ float g_xT[N_NODES * NC];
__device__ float g_ax[N_NODES * NC];
__device__ float g_M[384];    // folded x-path: [gate(3)][fin(2)][64]
__device__ float g_gb[192];   // folded gate bias: [gate(3)][64]

// ---------------- packed f32x2 helpers ----------------
typedef unsigned long long u64t;
__device__ __forceinline__ u64t pk2(float lo, float hi) {
    u64t r; asm("mov.b64 %0, {%1, %2};" : "=l"(r) : "f"(lo), "f"(hi)); return r;
}
__device__ __forceinline__ u64t dup2(float x) {
    u64t r; asm("mov.b64 %0, {%1, %1};" : "=l"(r) : "f"(x)); return r;
}
__device__ __forceinline__ void up2(float& lo, float& hi, u64t v) {
    asm("mov.b64 {%0, %1}, %2;" : "=f"(lo), "=f"(hi) : "l"(v));
}
__device__ __forceinline__ void fma2(u64t& d, u64t a, u64t b) {
    asm("fma.rn.f32x2 %0, %1, %2, %0;" : "+l"(d) : "l"(a), "l"(b));
}

__device__ __forceinline__ float fast_sigmoid(float v) {
    return __fdividef(1.f, 1.f + __expf(-v));
}
__device__ __forceinline__ float fast_tanh(float v) {
    float e = __expf(-2.f * fabsf(v));              // in (0,1] -> no overflow
    float th = __fdividef(1.f - e, 1.f + e);
    return copysignf(th, v);
}

// ---------------- init: deg=1 (self loop), count=0 ----------------
__global__ void k_init() {
    int i = blockIdx.x * blockDim.x + threadIdx.x;
    if (i < N_NODES) { g_deg[i] = 1.0f; g_count[i] = 0; }
}

// ---------------- transpose x [B,N,F,T] -> xT [N][ (b*2+f)*12+t ] ----------------
__global__ void k_xT(const float* __restrict__ x) {
    int i = blockIdx.x * blockDim.x + threadIdx.x;
    if (i >= N_NODES * NC) return;
    int n = i / NC, c = i % NC;
    int b = c / (FINF * TT);
    int rem = c % (FINF * TT);
    int f = rem / TT, t = rem % TT;
    g_xT[i] = x[(((size_t)b * N_NODES + n) * FINF + f) * TT + t];
}

// ---------------- per-edge degree + count ----------------
__global__ void k_edge(const int* __restrict__ ei, const float* __restrict__ ew, int E) {
    int e = blockIdx.x * blockDim.x + threadIdx.x;
    if (e >= E) return;
    int d = ei[E + e];
    atomicAdd(&g_deg[d], ew[e]);
    atomicAdd(&g_count[d], 1);
}

__global__ void k_dinv() {
    int n = blockIdx.x * blockDim.x + threadIdx.x;
    if (n < N_NODES) g_dinv[n] = rsqrtf(g_deg[n]);  // deg >= 1 always (self loop)
}

// ---------------- single-block exclusive scan of counts -> rowptr, cursor ----------------
__global__ void k_scan() {
    __shared__ int sums[1024];
    const int CH = 10;  // 1024*10 >= 10001
    int tid = threadIdx.x;
    int base = tid * CH;
    int local[CH];
    int s = 0;
    for (int j = 0; j < CH; j++) {
        int idx = base + j;
        int v = (idx < N_NODES) ? g_count[idx] : 0;
        local[j] = s;
        s += v;
    }
    sums[tid] = s;
    __syncthreads();
    for (int off = 1; off < 1024; off <<= 1) {
        int v = (tid >= off) ? sums[tid - off] : 0;
        __syncthreads();
        sums[tid] += v;
        __syncthreads();
    }
    int offset = (tid > 0) ? sums[tid - 1] : 0;
    for (int j = 0; j < CH; j++) {
        int idx = base + j;
        if (idx <= N_NODES) {
            int v = offset + local[j];
            g_rowptr[idx] = v;
            if (idx < N_NODES) g_cursor[idx] = v;
        }
    }
}

// ---------------- scatter edges into CSR with normalized weight ----------------
__global__ void k_scatter(const int* __restrict__ ei, const float* __restrict__ ew, int E) {
    int e = blockIdx.x * blockDim.x + threadIdx.x;
    if (e >= E) return;
    int s = ei[e];
    int d = ei[E + e];
    int pos = atomicAdd(&g_cursor[d], 1);
    g_csrc[pos] = s;
    g_cw[pos] = g_dinv[s] * ew[e] * g_dinv[d];
}

// ---------------- aggregate: ax[n] = sum_in norm * xT[src] + dinv^2 * xT[n] ----------------
__global__ void k_agg() {
    int warp = (blockIdx.x * blockDim.x + threadIdx.x) >> 5;
    int lane = threadIdx.x & 31;
    if (warp >= N_NODES) return;
    int n = warp;
    float dv = g_dinv[n];
    float self_w = dv * dv;
    float a0 = self_w * g_xT[(size_t)n * NC + lane];
    float a1 = self_w * g_xT[(size_t)n * NC + lane + 32];
    float a2 = self_w * g_xT[(size_t)n * NC + lane + 64];
    int e0 = g_rowptr[n], e1 = g_rowptr[n + 1];
    for (int e = e0; e < e1; e++) {
        int s = g_csrc[e];
        float w = g_cw[e];
        const float* xs = &g_xT[(size_t)s * NC];
        a0 += w * xs[lane];
        a1 += w * xs[lane + 32];
        a2 += w * xs[lane + 64];
    }
    g_ax[(size_t)n * NC + lane] = a0;
    g_ax[(size_t)n * NC + lane + 32] = a1;
    g_ax[(size_t)n * NC + lane + 64] = a2;
}

// ---------------- fold x-path matrices: M = W @ L_top, gb = b @ L_top + L_b ----------------
__global__ void k_fold(const float* __restrict__ Wz, const float* __restrict__ bz,
                       const float* __restrict__ Wr, const float* __restrict__ br,
                       const float* __restrict__ Wh, const float* __restrict__ bh,
                       const float* __restrict__ Lz, const float* __restrict__ Lzb,
                       const float* __restrict__ Lr, const float* __restrict__ Lrb,
                       const float* __restrict__ Lh, const float* __restrict__ Lhb) {
    int tid = threadIdx.x;  // 0..191
    if (tid >= 192) return;
    int g = tid >> 6, j = tid & 63;
    const float* W  = (g == 0) ? Wz  : (g == 1) ? Wr  : Wh;
    const float* bv = (g == 0) ? bz  : (g == 1) ? br  : bh;
    const float* L  = (g == 0) ? Lz  : (g == 1) ? Lr  : Lh;
    const float* Lb = (g == 0) ? Lzb : (g == 1) ? Lrb : Lhb;
    float m0 = 0.f, m1 = 0.f, gbv = 0.f;
    for (int m = 0; m < 64; m++) {
        float l = L[m * 64 + j];
        m0 += W[m] * l;
        m1 += W[64 + m] * l;
        gbv += bv[m] * l;
    }
    g_M[g * 128 + j] = m0;
    g_M[g * 128 + 64 + j] = m1;
    g_gb[g * 64 + j] = gbv + Lb[j];
}

// ---------------- persistent fused GRU: all 12 steps, H lives in SMEM ----------------
// smem (floats): sHT[64][266] sHrT[64][266] sW1[64][128] sW2[64][64] sLin[64][16]
//                sM[384] sGb[192] sLb[16] sAx[66][96]
#define SMEM_FLOATS (2*64*LDT + 64*128 + 64*64 + 64*16 + 384 + 192 + 16 + 66*96)

__global__ __launch_bounds__(NTHREADS, 1)
void k_steps(const float* __restrict__ Lz, const float* __restrict__ Lr,
             const float* __restrict__ Lh, const float* __restrict__ lw,
             const float* __restrict__ lb, float* __restrict__ out) {
    extern __shared__ float sm[];
    float* sHT  = sm;                 // transposed H: [k][row], ld=LDT
    float* sHrT = sHT + 64 * LDT;     // transposed H*R / relu(Hn)
    float* sW1  = sHrT + 64 * LDT;    // [k][0..63]=Lz_bot, [k][64..127]=Lr_bot
    float* sW2  = sW1 + 64 * 128;     // Lh_bot
    float* sLin = sW2 + 64 * 64;
    float* sM   = sLin + 64 * 16;
    float* sGb  = sM + 384;
    float* sLb  = sGb + 192;
    float* sAx  = sLb + 16;           // [66][96]

    int tid = threadIdx.x;
    int row0 = blockIdx.x * TILE_R;
    int n0 = blockIdx.x * (TILE_R / 4);   // 66 nodes per block

    // ---- one-time loads ----
    for (int i = tid; i < 64 * 128; i += NTHREADS) {
        int k = i >> 7, j = i & 127;
        sW1[i] = (j < 64) ? Lz[(64 + k) * 64 + j] : Lr[(64 + k) * 64 + (j - 64)];
    }
    for (int i = tid; i < 64 * 64; i += NTHREADS)
        sW2[i] = Lh[(64 + (i >> 6)) * 64 + (i & 63)];
    for (int i = tid; i < 64 * 16; i += NTHREADS) sLin[i] = lw[i];
    for (int i = tid; i < 384; i += NTHREADS) sM[i] = g_M[i];
    for (int i = tid; i < 192; i += NTHREADS) sGb[i] = g_gb[i];
    if (tid < 16) sLb[tid] = lb[tid];
    for (int i = tid; i < 66 * 96; i += NTHREADS) {
        int nn = i / 96, c = i % 96;
        int n = n0 + nn;
        sAx[i] = (n < N_NODES) ? g_ax[(size_t)n * NC + c] : 0.f;
    }
    for (int i = tid; i < 64 * LDT; i += NTHREADS) sHT[i] = 0.f;  // H0 = 0
    __syncthreads();

    int tx = tid & 15, ty = tid >> 4;     // ty 0..33
    bool comp = (ty < TY_COMPUTE);
    int rbase = ty * 8;                    // 8 rows per compute thread (4 pairs)
    int cz = tx * 4;                       // 4 gate columns per thread

    for (int t = 0; t < TT; t++) {
        // x-path contributions for this thread's rows
        float ax0[8], ax1[8];
        if (comp) {
#pragma unroll
            for (int i = 0; i < 8; i++) {
                int r = rbase + i;
                int nn = r >> 2, b = r & 3;
                ax0[i] = sAx[nn * 96 + (b * 2 + 0) * TT + t];
                ax1[i] = sAx[nn * 96 + (b * 2 + 1) * TT + t];
            }
        }

        // ---- pass A: R gate -> sHrT = H .* R ----
        if (comp) {
            u64t accR[4][4];
#pragma unroll
            for (int p = 0; p < 4; p++)
#pragma unroll
                for (int c = 0; c < 4; c++) {
                    int j = cz + c;
                    float lo = sGb[64 + j] + ax0[2 * p]     * sM[128 + j] + ax1[2 * p]     * sM[192 + j];
                    float hi = sGb[64 + j] + ax0[2 * p + 1] * sM[128 + j] + ax1[2 * p + 1] * sM[192 + j];
                    accR[p][c] = pk2(lo, hi);
                }
#pragma unroll 4
            for (int k = 0; k < 64; k++) {
                const u64t* ap = (const u64t*)(sHT + k * LDT + rbase);
                u64t a0 = ap[0], a1 = ap[1], a2 = ap[2], a3 = ap[3];
#pragma unroll
                for (int c = 0; c < 4; c++) {
                    u64t b = dup2(sW1[k * 128 + 64 + cz + c]);
                    fma2(accR[0][c], a0, b);
                    fma2(accR[1][c], a1, b);
                    fma2(accR[2][c], a2, b);
                    fma2(accR[3][c], a3, b);
                }
            }
#pragma unroll
            for (int p = 0; p < 4; p++)
#pragma unroll
                for (int c = 0; c < 4; c++) {
                    float lo, hi; up2(lo, hi, accR[p][c]);
                    int j = cz + c;
                    int i0 = j * LDT + rbase + 2 * p;
                    sHrT[i0]     = sHT[i0]     * fast_sigmoid(lo);
                    sHrT[i0 + 1] = sHT[i0 + 1] * fast_sigmoid(hi);
                }
        }
        __syncthreads();

        // ---- pass B: Z gate + candidate (reads sHT and sHrT) ----
        u64t accZ[4][4], accH[4][4];
        if (comp) {
#pragma unroll
            for (int p = 0; p < 4; p++)
#pragma unroll
                for (int c = 0; c < 4; c++) {
                    int j = cz + c;
                    float zl = sGb[j] + ax0[2 * p]     * sM[j] + ax1[2 * p]     * sM[64 + j];
                    float zh = sGb[j] + ax0[2 * p + 1] * sM[j] + ax1[2 * p + 1] * sM[64 + j];
                    accZ[p][c] = pk2(zl, zh);
                    float hl = sGb[128 + j] + ax0[2 * p]     * sM[256 + j] + ax1[2 * p]     * sM[320 + j];
                    float hh = sGb[128 + j] + ax0[2 * p + 1] * sM[256 + j] + ax1[2 * p + 1] * sM[320 + j];
                    accH[p][c] = pk2(hl, hh);
                }
#pragma unroll 2
            for (int k = 0; k < 64; k++) {
                const u64t* azp = (const u64t*)(sHT + k * LDT + rbase);
                const u64t* ahp = (const u64t*)(sHrT + k * LDT + rbase);
                u64t az0 = azp[0], az1 = azp[1], az2 = azp[2], az3 = azp[3];
                u64t ah0 = ahp[0], ah1 = ahp[1], ah2 = ahp[2], ah3 = ahp[3];
#pragma unroll
                for (int c = 0; c < 4; c++) {
                    u64t bz = dup2(sW1[k * 128 + cz + c]);
                    fma2(accZ[0][c], az0, bz);
                    fma2(accZ[1][c], az1, bz);
                    fma2(accZ[2][c], az2, bz);
                    fma2(accZ[3][c], az3, bz);
                    u64t bh = dup2(sW2[k * 64 + cz + c]);
                    fma2(accH[0][c], ah0, bh);
                    fma2(accH[1][c], ah1, bh);
                    fma2(accH[2][c], ah2, bh);
                    fma2(accH[3][c], ah3, bh);
                }
            }
        }
        __syncthreads();   // all k-loop reads of sHT/sHrT complete

        // ---- state update: Hn -> sHT (next step), relu(Hn) -> sHrT, Hn external? none ----
        if (comp) {
#pragma unroll
            for (int p = 0; p < 4; p++)
#pragma unroll
                for (int c = 0; c < 4; c++) {
                    float zl, zh, hl, hh;
                    up2(zl, zh, accZ[p][c]);
                    up2(hl, hh, accH[p][c]);
                    int j = cz + c;
                    int i0 = j * LDT + rbase + 2 * p;
                    float z0 = fast_sigmoid(zl), z1 = fast_sigmoid(zh);
                    float t0 = fast_tanh(hl),   t1 = fast_tanh(hh);
                    float hn0 = z0 * sHT[i0]     + (1.f - z0) * t0;
                    float hn1 = z1 * sHT[i0 + 1] + (1.f - z1) * t1;
                    sHT[i0] = hn0;       sHT[i0 + 1] = hn1;
                    sHrT[i0] = fmaxf(hn0, 0.f);
                    sHrT[i0 + 1] = fmaxf(hn1, 0.f);
                }
        }
        __syncthreads();

        // ---- GEMM3: out = relu(Hn) @ lin_w + lin_b ----
        if (tid < 2 * TILE_R) {
            int r3 = tid >> 1;
            int o0 = (tid & 1) * 8;
            u64t acc4[4];
#pragma unroll
            for (int q = 0; q < 4; q++) acc4[q] = pk2(sLb[o0 + 2 * q], sLb[o0 + 2 * q + 1]);
#pragma unroll 4
            for (int k = 0; k < 64; k++) {
                u64t a = dup2(sHrT[k * LDT + r3]);
                const u64t* bp = (const u64t*)(sLin + k * 16 + o0);
                fma2(acc4[0], a, bp[0]);
                fma2(acc4[1], a, bp[1]);
                fma2(acc4[2], a, bp[2]);
                fma2(acc4[3], a, bp[3]);
            }
            int row = row0 + r3;
            if (row < NB) {
                int n = row >> 2, b = row & 3;
                float* op = out + ((((size_t)b * TT + t) * N_NODES + n) * OUTD + o0);
#pragma unroll
                for (int q = 0; q < 4; q++) {
                    float lo, hi; up2(lo, hi, acc4[q]);
                    op[2 * q] = lo; op[2 * q + 1] = hi;
                }
            }
        }
        __syncthreads();   // protect sHrT before next step's pass A writes
    }
}

// ---------------- launch ----------------
extern "C" void kernel_launch(void* const* d_in, const int* in_sizes, int n_in,
                              void* d_out, int out_size) {
    const float* x   = (const float*)d_in[0];
    const int*   ei  = (const int*)d_in[1];
    const float* ew  = (const float*)d_in[2];
    const float* Wz  = (const float*)d_in[3];
    const float* bz  = (const float*)d_in[4];
    const float* Wr  = (const float*)d_in[5];
    const float* br  = (const float*)d_in[6];
    const float* Wh  = (const float*)d_in[7];
    const float* bh  = (const float*)d_in[8];
    const float* Lz  = (const float*)d_in[9];
    const float* Lzb = (const float*)d_in[10];
    const float* Lr  = (const float*)d_in[11];
    const float* Lrb = (const float*)d_in[12];
    const float* Lh  = (const float*)d_in[13];
    const float* Lhb = (const float*)d_in[14];
    const float* lw  = (const float*)d_in[15];
    const float* lb  = (const float*)d_in[16];
    float* out = (float*)d_out;

    int E = in_sizes[2];
    if (E > N_EDGES_MAX) E = N_EDGES_MAX;

    const int smem_bytes = SMEM_FLOATS * (int)sizeof(float);
    cudaFuncSetAttribute(k_steps, cudaFuncAttributeMaxDynamicSharedMemorySize, smem_bytes);

    k_init<<<(N_NODES + 255) / 256, 256>>>();
    k_xT<<<(N_NODES * NC + 255) / 256, 256>>>(x);
    k_edge<<<(E + 255) / 256, 256>>>(ei, ew, E);
    k_dinv<<<(N_NODES + 255) / 256, 256>>>();
    k_scan<<<1, 1024>>>();
    k_scatter<<<(E + 255) / 256, 256>>>(ei, ew, E);
    k_agg<<<(N_NODES + 7) / 8, 256>>>();
    k_fold<<<1, 192>>>(Wz, bz, Wr, br, Wh, bh, Lz, Lzb, Lr, Lrb, Lh, Lhb);

    int grid = (NB + TILE_R - 1) / TILE_R;   // 152 blocks = exactly one wave
    k_steps<<<grid, NTHREADS, smem_bytes>>>(Lz, Lr, Lh, lw, lb, out);
}

// round 3
// speedup vs baseline: 2.0777x; 1.3684x over previous
#include <cuda_runtime.h>
#include <cstdint>

#define N_NODES 10000
#define N_EDGES_MAX 320000
#define BB 4
#define TT 12
#define FINF 2
#define HID 64
#define OUTD 16
#define NB (N_NODES*BB)        /* 40000 rows (n,b) */
#define NC (BB*FINF*TT)        /* 96 features per node */

#define TILE_R 272             /* rows per block: 148 blocks = 1 wave on 152 SMs */
#define NTHREADS 272           /* 17 ty * 16 tx ; each thread 16 rows x 4 cols */
#define GRID_STEPS 148
#define NODES_PER_BLK 68       /* 272/4 */
#define LDT 274                /* transposed tile leading dim */

// ---------------- device scratch ----------------
__device__ float g_deg[N_NODES];
__device__ float g_dinv[N_NODES];
__device__ int   g_count[N_NODES];
__device__ int   g_rowptr[N_NODES + 1];
__device__ int   g_cursor[N_NODES];
__device__ int   g_csrc[N_EDGES_MAX];
__device__ float g_cw[N_EDGES_MAX];
__device__ float g_xT[N_NODES * NC];
__device__ float g_ax[N_NODES * NC];
__device__ float g_M[384];    // folded x-path: [gate(3)][fin(2)][64]
__device__ float g_gb[192];   // folded gate bias

// ---------------- packed f32x2 helpers ----------------
typedef unsigned long long u64t;
__device__ __forceinline__ u64t pk2(float lo, float hi) {
    u64t r; asm("mov.b64 %0, {%1, %2};" : "=l"(r) : "f"(lo), "f"(hi)); return r;
}
__device__ __forceinline__ u64t dup2(float x) {
    u64t r; asm("mov.b64 %0, {%1, %1};" : "=l"(r) : "f"(x)); return r;
}
__device__ __forceinline__ void up2(float& lo, float& hi, u64t v) {
    asm("mov.b64 {%0, %1}, %2;" : "=f"(lo), "=f"(hi) : "l"(v));
}
__device__ __forceinline__ void fma2(u64t& d, u64t a, u64t b) {
    asm("fma.rn.f32x2 %0, %1, %2, %0;" : "+l"(d) : "l"(a), "l"(b));
}

__device__ __forceinline__ float fast_sigmoid(float v) {
    return __fdividef(1.f, 1.f + __expf(-v));
}
__device__ __forceinline__ float fast_tanh(float v) {
    float e = __expf(-2.f * fabsf(v));
    float th = __fdividef(1.f - e, 1.f + e);
    return copysignf(th, v);
}

// ---------------- launch 1: transpose x + init deg/count ----------------
__global__ void k_xT_zero(const float* __restrict__ x) {
    int i = blockIdx.x * blockDim.x + threadIdx.x;
    if (i < N_NODES) { g_deg[i] = 1.0f; g_count[i] = 0; }
    if (i >= N_NODES * NC) return;
    int n = i / NC, c = i % NC;
    int b = c / (FINF * TT);
    int rem = c % (FINF * TT);
    int f = rem / TT, t = rem % TT;
    g_xT[i] = x[(((size_t)b * N_NODES + n) * FINF + f) * TT + t];
}

// ---------------- launch 2: per-edge degree + count ----------------
__global__ void k_edge(const int* __restrict__ ei, const float* __restrict__ ew, int E) {
    int e = blockIdx.x * blockDim.x + threadIdx.x;
    if (e >= E) return;
    int d = ei[E + e];
    atomicAdd(&g_deg[d], ew[e]);
    atomicAdd(&g_count[d], 1);
}

// ---------------- launch 3: scan counts -> rowptr/cursor, and dinv ----------------
__global__ void k_scan_dinv() {
    __shared__ int sums[1024];
    const int CH = 10;
    int tid = threadIdx.x;
    int base = tid * CH;
    int local[CH];
    int s = 0;
    for (int j = 0; j < CH; j++) {
        int idx = base + j;
        int v = (idx < N_NODES) ? g_count[idx] : 0;
        local[j] = s;
        s += v;
    }
    sums[tid] = s;
    __syncthreads();
    for (int off = 1; off < 1024; off <<= 1) {
        int v = (tid >= off) ? sums[tid - off] : 0;
        __syncthreads();
        sums[tid] += v;
        __syncthreads();
    }
    int offset = (tid > 0) ? sums[tid - 1] : 0;
    for (int j = 0; j < CH; j++) {
        int idx = base + j;
        if (idx <= N_NODES) {
            int v = offset + local[j];
            g_rowptr[idx] = v;
            if (idx < N_NODES) g_cursor[idx] = v;
        }
    }
    for (int n = tid; n < N_NODES; n += 1024)
        g_dinv[n] = rsqrtf(g_deg[n]);
}

// ---------------- launch 4: scatter edges into CSR with normalized weight ----------------
__global__ void k_scatter(const int* __restrict__ ei, const float* __restrict__ ew, int E) {
    int e = blockIdx.x * blockDim.x + threadIdx.x;
    if (e >= E) return;
    int s = ei[e];
    int d = ei[E + e];
    int pos = atomicAdd(&g_cursor[d], 1);
    g_csrc[pos] = s;
    g_cw[pos] = g_dinv[s] * ew[e] * g_dinv[d];
}

// ---------------- launch 5: aggregate + fold (fold in last block) ----------------
__global__ void k_agg_fold(const float* __restrict__ Wz, const float* __restrict__ bz,
                           const float* __restrict__ Wr, const float* __restrict__ br,
                           const float* __restrict__ Wh, const float* __restrict__ bh,
                           const float* __restrict__ Lz, const float* __restrict__ Lzb,
                           const float* __restrict__ Lr, const float* __restrict__ Lrb,
                           const float* __restrict__ Lh, const float* __restrict__ Lhb) {
    if (blockIdx.x == gridDim.x - 1) {
        int tid = threadIdx.x;
        if (tid >= 192) return;
        int g = tid >> 6, j = tid & 63;
        const float* W  = (g == 0) ? Wz  : (g == 1) ? Wr  : Wh;
        const float* bv = (g == 0) ? bz  : (g == 1) ? br  : bh;
        const float* L  = (g == 0) ? Lz  : (g == 1) ? Lr  : Lh;
        const float* Lb = (g == 0) ? Lzb : (g == 1) ? Lrb : Lhb;
        float m0 = 0.f, m1 = 0.f, gbv = 0.f;
        for (int m = 0; m < 64; m++) {
            float l = L[m * 64 + j];
            m0 += W[m] * l;
            m1 += W[64 + m] * l;
            gbv += bv[m] * l;
        }
        g_M[g * 128 + j] = m0;
        g_M[g * 128 + 64 + j] = m1;
        g_gb[g * 64 + j] = gbv + Lb[j];
        return;
    }
    int warp = (blockIdx.x * blockDim.x + threadIdx.x) >> 5;
    int lane = threadIdx.x & 31;
    if (warp >= N_NODES) return;
    int n = warp;
    float dv = g_dinv[n];
    float self_w = dv * dv;
    float a0 = self_w * g_xT[(size_t)n * NC + lane];
    float a1 = self_w * g_xT[(size_t)n * NC + lane + 32];
    float a2 = self_w * g_xT[(size_t)n * NC + lane + 64];
    int e0 = g_rowptr[n], e1 = g_rowptr[n + 1];
    for (int e = e0; e < e1; e++) {
        int s = g_csrc[e];
        float w = g_cw[e];
        const float* xs = &g_xT[(size_t)s * NC];
        a0 += w * xs[lane];
        a1 += w * xs[lane + 32];
        a2 += w * xs[lane + 64];
    }
    g_ax[(size_t)n * NC + lane] = a0;
    g_ax[(size_t)n * NC + lane + 32] = a1;
    g_ax[(size_t)n * NC + lane + 64] = a2;
}

// ---------------- launch 6: persistent fused GRU, all 12 steps ----------------
// smem (floats): sHT[64][274] sHrT[64][274] sW1[64][128] sW2[64][64] sLin[64][16]
//                sM[384] sGb[192] sLb[16] sAx[68][96]
#define SMEM_FLOATS (2*64*LDT + 64*128 + 64*64 + 64*16 + 384 + 192 + 16 + NODES_PER_BLK*96)

__global__ __launch_bounds__(NTHREADS, 1)
void k_steps(const float* __restrict__ Lz, const float* __restrict__ Lr,
             const float* __restrict__ Lh, const float* __restrict__ lw,
             const float* __restrict__ lb, float* __restrict__ out) {
    extern __shared__ float sm[];
    float* sHT  = sm;                 // transposed H: [k][row]
    float* sHrT = sHT + 64 * LDT;     // transposed H*R / relu(Hn)
    float* sW1  = sHrT + 64 * LDT;    // [k][0..63]=Lz_bot, [k][64..127]=Lr_bot
    float* sW2  = sW1 + 64 * 128;     // Lh_bot
    float* sLin = sW2 + 64 * 64;
    float* sM   = sLin + 64 * 16;
    float* sGb  = sM + 384;
    float* sLb  = sGb + 192;
    float* sAx  = sLb + 16;           // [68][96]

    int tid = threadIdx.x;
    int row0 = blockIdx.x * TILE_R;
    int n0 = blockIdx.x * NODES_PER_BLK;

    // ---- one-time loads ----
    for (int i = tid; i < 64 * 128; i += NTHREADS) {
        int k = i >> 7, j = i & 127;
        sW1[i] = (j < 64) ? Lz[(64 + k) * 64 + j] : Lr[(64 + k) * 64 + (j - 64)];
    }
    for (int i = tid; i < 64 * 64; i += NTHREADS)
        sW2[i] = Lh[(64 + (i >> 6)) * 64 + (i & 63)];
    for (int i = tid; i < 64 * 16; i += NTHREADS) sLin[i] = lw[i];
    for (int i = tid; i < 384; i += NTHREADS) sM[i] = g_M[i];
    for (int i = tid; i < 192; i += NTHREADS) sGb[i] = g_gb[i];
    if (tid < 16) sLb[tid] = lb[tid];
    for (int i = tid; i < NODES_PER_BLK * 96; i += NTHREADS) {
        int nn = i / 96, c = i % 96;
        int n = n0 + nn;
        sAx[i] = (n < N_NODES) ? g_ax[(size_t)n * NC + c] : 0.f;
    }
    for (int i = tid; i < 64 * LDT; i += NTHREADS) sHT[i] = 0.f;  // H0 = 0
    __syncthreads();

    int tx = tid & 15, ty = tid >> 4;     // ty 0..16
    int rbase = ty * 16;                   // 16 rows per thread (8 pairs)
    int cz = tx * 4;                       // 4 gate columns per thread

    for (int t = 0; t < TT; t++) {
        // =========== pass R: accR = [ax,H] @ Lr ; sHrT = H .* sigmoid(accR) ===========
        u64t accR[8][4];
#pragma unroll
        for (int p = 0; p < 8; p++) {
            int r_0 = rbase + 2 * p, r_1 = r_0 + 1;
            int nn0 = r_0 >> 2, b0 = r_0 & 3;
            int nn1 = r_1 >> 2, b1 = r_1 & 3;
            float a00 = sAx[nn0 * 96 + (b0 * 2 + 0) * TT + t];
            float a01 = sAx[nn0 * 96 + (b0 * 2 + 1) * TT + t];
            float a10 = sAx[nn1 * 96 + (b1 * 2 + 0) * TT + t];
            float a11 = sAx[nn1 * 96 + (b1 * 2 + 1) * TT + t];
#pragma unroll
            for (int c = 0; c < 4; c++) {
                int j = cz + c;
                float lo = sGb[64 + j] + a00 * sM[128 + j] + a01 * sM[192 + j];
                float hi = sGb[64 + j] + a10 * sM[128 + j] + a11 * sM[192 + j];
                accR[p][c] = pk2(lo, hi);
            }
        }
#pragma unroll 2
        for (int k = 0; k < 64; k++) {
            const u64t* ap = (const u64t*)(sHT + k * LDT + rbase);
            u64t a0 = ap[0], a1 = ap[1], a2 = ap[2], a3 = ap[3];
            u64t a4 = ap[4], a5 = ap[5], a6 = ap[6], a7 = ap[7];
#pragma unroll
            for (int c = 0; c < 4; c++) {
                u64t b = dup2(sW1[k * 128 + 64 + cz + c]);
                fma2(accR[0][c], a0, b); fma2(accR[1][c], a1, b);
                fma2(accR[2][c], a2, b); fma2(accR[3][c], a3, b);
                fma2(accR[4][c], a4, b); fma2(accR[5][c], a5, b);
                fma2(accR[6][c], a6, b); fma2(accR[7][c], a7, b);
            }
        }
#pragma unroll
        for (int p = 0; p < 8; p++)
#pragma unroll
            for (int c = 0; c < 4; c++) {
                float lo, hi; up2(lo, hi, accR[p][c]);
                int i0 = (cz + c) * LDT + rbase + 2 * p;
                float h0, h1; up2(h0, h1, *(const u64t*)(sHT + i0));
                *(u64t*)(sHrT + i0) = pk2(h0 * fast_sigmoid(lo), h1 * fast_sigmoid(hi));
            }

        // =========== pass Z (reads sHT only; before sync to overlap) ===========
        u64t zpk[8][4];
#pragma unroll
        for (int p = 0; p < 8; p++) {
            int r_0 = rbase + 2 * p, r_1 = r_0 + 1;
            int nn0 = r_0 >> 2, b0 = r_0 & 3;
            int nn1 = r_1 >> 2, b1 = r_1 & 3;
            float a00 = sAx[nn0 * 96 + (b0 * 2 + 0) * TT + t];
            float a01 = sAx[nn0 * 96 + (b0 * 2 + 1) * TT + t];
            float a10 = sAx[nn1 * 96 + (b1 * 2 + 0) * TT + t];
            float a11 = sAx[nn1 * 96 + (b1 * 2 + 1) * TT + t];
#pragma unroll
            for (int c = 0; c < 4; c++) {
                int j = cz + c;
                float lo = sGb[j] + a00 * sM[j] + a01 * sM[64 + j];
                float hi = sGb[j] + a10 * sM[j] + a11 * sM[64 + j];
                zpk[p][c] = pk2(lo, hi);
            }
        }
#pragma unroll 2
        for (int k = 0; k < 64; k++) {
            const u64t* ap = (const u64t*)(sHT + k * LDT + rbase);
            u64t a0 = ap[0], a1 = ap[1], a2 = ap[2], a3 = ap[3];
            u64t a4 = ap[4], a5 = ap[5], a6 = ap[6], a7 = ap[7];
#pragma unroll
            for (int c = 0; c < 4; c++) {
                u64t b = dup2(sW1[k * 128 + cz + c]);
                fma2(zpk[0][c], a0, b); fma2(zpk[1][c], a1, b);
                fma2(zpk[2][c], a2, b); fma2(zpk[3][c], a3, b);
                fma2(zpk[4][c], a4, b); fma2(zpk[5][c], a5, b);
                fma2(zpk[6][c], a6, b); fma2(zpk[7][c], a7, b);
            }
        }
        // apply sigmoid, keep packed Z
#pragma unroll
        for (int p = 0; p < 8; p++)
#pragma unroll
            for (int c = 0; c < 4; c++) {
                float lo, hi; up2(lo, hi, zpk[p][c]);
                zpk[p][c] = pk2(fast_sigmoid(lo), fast_sigmoid(hi));
            }
        __syncthreads();   // sHrT fully written; all sHT reads of R/Z done

        // =========== pass H: candidate = [ax, H.*R] @ Lh ===========
        u64t accH[8][4];
#pragma unroll
        for (int p = 0; p < 8; p++) {
            int r_0 = rbase + 2 * p, r_1 = r_0 + 1;
            int nn0 = r_0 >> 2, b0 = r_0 & 3;
            int nn1 = r_1 >> 2, b1 = r_1 & 3;
            float a00 = sAx[nn0 * 96 + (b0 * 2 + 0) * TT + t];
            float a01 = sAx[nn0 * 96 + (b0 * 2 + 1) * TT + t];
            float a10 = sAx[nn1 * 96 + (b1 * 2 + 0) * TT + t];
            float a11 = sAx[nn1 * 96 + (b1 * 2 + 1) * TT + t];
#pragma unroll
            for (int c = 0; c < 4; c++) {
                int j = cz + c;
                float lo = sGb[128 + j] + a00 * sM[256 + j] + a01 * sM[320 + j];
                float hi = sGb[128 + j] + a10 * sM[256 + j] + a11 * sM[320 + j];
                accH[p][c] = pk2(lo, hi);
            }
        }
#pragma unroll 2
        for (int k = 0; k < 64; k++) {
            const u64t* ap = (const u64t*)(sHrT + k * LDT + rbase);
            u64t a0 = ap[0], a1 = ap[1], a2 = ap[2], a3 = ap[3];
            u64t a4 = ap[4], a5 = ap[5], a6 = ap[6], a7 = ap[7];
#pragma unroll
            for (int c = 0; c < 4; c++) {
                u64t b = dup2(sW2[k * 64 + cz + c]);
                fma2(accH[0][c], a0, b); fma2(accH[1][c], a1, b);
                fma2(accH[2][c], a2, b); fma2(accH[3][c], a3, b);
                fma2(accH[4][c], a4, b); fma2(accH[5][c], a5, b);
                fma2(accH[6][c], a6, b); fma2(accH[7][c], a7, b);
            }
        }
        __syncthreads();   // all sHrT reads complete before overwrite

        // =========== update: Hn -> sHT ; relu(Hn) -> sHrT ===========
#pragma unroll
        for (int p = 0; p < 8; p++)
#pragma unroll
            for (int c = 0; c < 4; c++) {
                float z0, z1, hl, hh;
                up2(z0, z1, zpk[p][c]);
                up2(hl, hh, accH[p][c]);
                int i0 = (cz + c) * LDT + rbase + 2 * p;
                float h0, h1; up2(h0, h1, *(const u64t*)(sHT + i0));
                float t0 = fast_tanh(hl), t1 = fast_tanh(hh);
                float hn0 = z0 * h0 + (1.f - z0) * t0;
                float hn1 = z1 * h1 + (1.f - z1) * t1;
                *(u64t*)(sHT + i0) = pk2(hn0, hn1);
                *(u64t*)(sHrT + i0) = pk2(fmaxf(hn0, 0.f), fmaxf(hn1, 0.f));
            }
        __syncthreads();

        // =========== GEMM3: out = relu(Hn) @ lin_w + lin_b (1 row x 16 outs/thread) ===========
        {
            int r3 = tid;   // 0..271
            u64t acc[8];
#pragma unroll
            for (int q = 0; q < 8; q++) acc[q] = pk2(sLb[2 * q], sLb[2 * q + 1]);
#pragma unroll 4
            for (int k = 0; k < 64; k++) {
                u64t a = dup2(sHrT[k * LDT + r3]);
                const u64t* bp = (const u64t*)(sLin + k * 16);
                fma2(acc[0], a, bp[0]); fma2(acc[1], a, bp[1]);
                fma2(acc[2], a, bp[2]); fma2(acc[3], a, bp[3]);
                fma2(acc[4], a, bp[4]); fma2(acc[5], a, bp[5]);
                fma2(acc[6], a, bp[6]); fma2(acc[7], a, bp[7]);
            }
            int row = row0 + r3;
            if (row < NB) {
                int n = row >> 2, b = row & 3;
                float4* op = (float4*)(out + ((((size_t)b * TT + t) * N_NODES + n) * OUTD));
#pragma unroll
                for (int q = 0; q < 4; q++) {
                    float x0, x1, x2, x3;
                    up2(x0, x1, acc[2 * q]);
                    up2(x2, x3, acc[2 * q + 1]);
                    op[q] = make_float4(x0, x1, x2, x3);
                }
            }
        }
        __syncthreads();   // GEMM3 reads of sHrT done before next pass R writes
    }
}

// ---------------- launch ----------------
extern "C" void kernel_launch(void* const* d_in, const int* in_sizes, int n_in,
                              void* d_out, int out_size) {
    const float* x   = (const float*)d_in[0];
    const int*   ei  = (const int*)d_in[1];
    const float* ew  = (const float*)d_in[2];
    const float* Wz  = (const float*)d_in[3];
    const float* bz  = (const float*)d_in[4];
    const float* Wr  = (const float*)d_in[5];
    const float* br  = (const float*)d_in[6];
    const float* Wh  = (const float*)d_in[7];
    const float* bh  = (const float*)d_in[8];
    const float* Lz  = (const float*)d_in[9];
    const float* Lzb = (const float*)d_in[10];
    const float* Lr  = (const float*)d_in[11];
    const float* Lrb = (const float*)d_in[12];
    const float* Lh  = (const float*)d_in[13];
    const float* Lhb = (const float*)d_in[14];
    const float* lw  = (const float*)d_in[15];
    const float* lb  = (const float*)d_in[16];
    float* out = (float*)d_out;

    int E = in_sizes[2];
    if (E > N_EDGES_MAX) E = N_EDGES_MAX;

    const int smem_bytes = SMEM_FLOATS * (int)sizeof(float);
    cudaFuncSetAttribute(k_steps, cudaFuncAttributeMaxDynamicSharedMemorySize, smem_bytes);

    // 6 launches; ncu (-s 5 -c 1) captures launch #6 = k_steps
    k_xT_zero<<<(N_NODES * NC + 255) / 256, 256>>>(x);
    k_edge<<<(E + 255) / 256, 256>>>(ei, ew, E);
    k_scan_dinv<<<1, 1024>>>();
    k_scatter<<<(E + 255) / 256, 256>>>(ei, ew, E);
    k_agg_fold<<<(N_NODES + 7) / 8 + 1, 256>>>(Wz, bz, Wr, br, Wh, bh,
                                               Lz, Lzb, Lr, Lrb, Lh, Lhb);
    k_steps<<<GRID_STEPS, NTHREADS, smem_bytes>>>(Lz, Lr, Lh, lw, lb, out);
}

// round 4
// speedup vs baseline: 2.2689x; 1.0920x over previous
#include <cuda_runtime.h>
#include <cstdint>

#define N_NODES 10000
#define N_EDGES_MAX 320000
#define BB 4
#define TT 12
#define FINF 2
#define HID 64
#define OUTD 16
#define NB (N_NODES*BB)        /* 40000 rows (n,b) */
#define NC (BB*FINF*TT)        /* 96 features per node */

#define TILE_R 272             /* rows per block: 148 blocks = 1 wave */
#define NTHREADS 544           /* 34 ty * 16 tx ; each thread 8 rows x 4 cols */
#define GRID_STEPS 148
#define NODES_PER_BLK 68       /* 272/4 */
#define LDT 274                /* transposed tile leading dim */

// ---------------- device scratch ----------------
__device__ float g_deg[N_NODES];
__device__ float g_dinv[N_NODES];
__device__ int   g_count[N_NODES];
__device__ int   g_rowptr[N_NODES + 1];
__device__ int   g_cursor[N_NODES];
__device__ int   g_csrc[N_EDGES_MAX];
__device__ float g_cw[N_EDGES_MAX];
__device__ float g_xT[N_NODES * NC];
__device__ float g_ax[N_NODES * NC];
__device__ float g_M[384];    // folded x-path: [gate(3)][fin(2)][64]
__device__ float g_gb[192];   // folded gate bias

// ---------------- packed f32x2 helpers ----------------
typedef unsigned long long u64t;
__device__ __forceinline__ u64t pk2(float lo, float hi) {
    u64t r; asm("mov.b64 %0, {%1, %2};" : "=l"(r) : "f"(lo), "f"(hi)); return r;
}
__device__ __forceinline__ u64t dup2(float x) {
    u64t r; asm("mov.b64 %0, {%1, %1};" : "=l"(r) : "f"(x)); return r;
}
__device__ __forceinline__ void up2(float& lo, float& hi, u64t v) {
    asm("mov.b64 {%0, %1}, %2;" : "=f"(lo), "=f"(hi) : "l"(v));
}
__device__ __forceinline__ void fma2(u64t& d, u64t a, u64t b) {
    asm("fma.rn.f32x2 %0, %1, %2, %0;" : "+l"(d) : "l"(a), "l"(b));
}

__device__ __forceinline__ float fast_sigmoid(float v) {
    return __fdividef(1.f, 1.f + __expf(-v));
}
__device__ __forceinline__ float fast_tanh(float v) {
    float e = __expf(-2.f * fabsf(v));
    float th = __fdividef(1.f - e, 1.f + e);
    return copysignf(th, v);
}

// ---------------- launch 1: transpose x + init deg/count ----------------
__global__ void k_xT_zero(const float* __restrict__ x) {
    int i = blockIdx.x * blockDim.x + threadIdx.x;
    if (i < N_NODES) { g_deg[i] = 1.0f; g_count[i] = 0; }
    if (i >= N_NODES * NC) return;
    int n = i / NC, c = i % NC;
    int b = c / (FINF * TT);
    int rem = c % (FINF * TT);
    int f = rem / TT, t = rem % TT;
    g_xT[i] = x[(((size_t)b * N_NODES + n) * FINF + f) * TT + t];
}

// ---------------- launch 2: per-edge degree + count ----------------
__global__ void k_edge(const int* __restrict__ ei, const float* __restrict__ ew, int E) {
    int e = blockIdx.x * blockDim.x + threadIdx.x;
    if (e >= E) return;
    int d = ei[E + e];
    atomicAdd(&g_deg[d], ew[e]);
    atomicAdd(&g_count[d], 1);
}

// ---------------- launch 3: scan counts -> rowptr/cursor, and dinv ----------------
__global__ void k_scan_dinv() {
    __shared__ int sums[1024];
    const int CH = 10;
    int tid = threadIdx.x;
    int base = tid * CH;
    int local[CH];
    int s = 0;
    for (int j = 0; j < CH; j++) {
        int idx = base + j;
        int v = (idx < N_NODES) ? g_count[idx] : 0;
        local[j] = s;
        s += v;
    }
    sums[tid] = s;
    __syncthreads();
    for (int off = 1; off < 1024; off <<= 1) {
        int v = (tid >= off) ? sums[tid - off] : 0;
        __syncthreads();
        sums[tid] += v;
        __syncthreads();
    }
    int offset = (tid > 0) ? sums[tid - 1] : 0;
    for (int j = 0; j < CH; j++) {
        int idx = base + j;
        if (idx <= N_NODES) {
            int v = offset + local[j];
            g_rowptr[idx] = v;
            if (idx < N_NODES) g_cursor[idx] = v;
        }
    }
    for (int n = tid; n < N_NODES; n += 1024)
        g_dinv[n] = rsqrtf(g_deg[n]);
}

// ---------------- launch 4: scatter edges into CSR with normalized weight ----------------
__global__ void k_scatter(const int* __restrict__ ei, const float* __restrict__ ew, int E) {
    int e = blockIdx.x * blockDim.x + threadIdx.x;
    if (e >= E) return;
    int s = ei[e];
    int d = ei[E + e];
    int pos = atomicAdd(&g_cursor[d], 1);
    g_csrc[pos] = s;
    g_cw[pos] = g_dinv[s] * ew[e] * g_dinv[d];
}

// ---------------- launch 5: aggregate + fold (fold in last block) ----------------
__global__ void k_agg_fold(const float* __restrict__ Wz, const float* __restrict__ bz,
                           const float* __restrict__ Wr, const float* __restrict__ br,
                           const float* __restrict__ Wh, const float* __restrict__ bh,
                           const float* __restrict__ Lz, const float* __restrict__ Lzb,
                           const float* __restrict__ Lr, const float* __restrict__ Lrb,
                           const float* __restrict__ Lh, const float* __restrict__ Lhb) {
    if (blockIdx.x == gridDim.x - 1) {
        int tid = threadIdx.x;
        if (tid >= 192) return;
        int g = tid >> 6, j = tid & 63;
        const float* W  = (g == 0) ? Wz  : (g == 1) ? Wr  : Wh;
        const float* bv = (g == 0) ? bz  : (g == 1) ? br  : bh;
        const float* L  = (g == 0) ? Lz  : (g == 1) ? Lr  : Lh;
        const float* Lb = (g == 0) ? Lzb : (g == 1) ? Lrb : Lhb;
        float m0 = 0.f, m1 = 0.f, gbv = 0.f;
        for (int m = 0; m < 64; m++) {
            float l = L[m * 64 + j];
            m0 += W[m] * l;
            m1 += W[64 + m] * l;
            gbv += bv[m] * l;
        }
        g_M[g * 128 + j] = m0;
        g_M[g * 128 + 64 + j] = m1;
        g_gb[g * 64 + j] = gbv + Lb[j];
        return;
    }
    int warp = (blockIdx.x * blockDim.x + threadIdx.x) >> 5;
    int lane = threadIdx.x & 31;
    if (warp >= N_NODES) return;
    int n = warp;
    float dv = g_dinv[n];
    float self_w = dv * dv;
    float a0 = self_w * g_xT[(size_t)n * NC + lane];
    float a1 = self_w * g_xT[(size_t)n * NC + lane + 32];
    float a2 = self_w * g_xT[(size_t)n * NC + lane + 64];
    int e0 = g_rowptr[n], e1 = g_rowptr[n + 1];
    for (int e = e0; e < e1; e++) {
        int s = g_csrc[e];
        float w = g_cw[e];
        const float* xs = &g_xT[(size_t)s * NC];
        a0 += w * xs[lane];
        a1 += w * xs[lane + 32];
        a2 += w * xs[lane + 64];
    }
    g_ax[(size_t)n * NC + lane] = a0;
    g_ax[(size_t)n * NC + lane + 32] = a1;
    g_ax[(size_t)n * NC + lane + 64] = a2;
}

// ---------------- launch 6: persistent fused GRU, all 12 steps ----------------
// smem (floats): sHT[64][274] sHrT[64][274] sW1[64][128] sW2[64][64] sLin[64][16]
//                sM[384] sGb[192] sLb[16] sAx[68][96]
#define SMEM_FLOATS (2*64*LDT + 64*128 + 64*64 + 64*16 + 384 + 192 + 16 + NODES_PER_BLK*96)

__global__ __launch_bounds__(NTHREADS, 1)
void k_steps(const float* __restrict__ Lz, const float* __restrict__ Lr,
             const float* __restrict__ Lh, const float* __restrict__ lw,
             const float* __restrict__ lb, float* __restrict__ out) {
    extern __shared__ float sm[];
    float* sHT  = sm;                 // transposed H: [k][row]
    float* sHrT = sHT + 64 * LDT;     // transposed H*R / relu(Hn)
    float* sW1  = sHrT + 64 * LDT;    // [k][0..63]=Lz_bot, [k][64..127]=Lr_bot
    float* sW2  = sW1 + 64 * 128;     // Lh_bot
    float* sLin = sW2 + 64 * 64;
    float* sM   = sLin + 64 * 16;
    float* sGb  = sM + 384;
    float* sLb  = sGb + 192;
    float* sAx  = sLb + 16;           // [68][96]

    int tid = threadIdx.x;
    int row0 = blockIdx.x * TILE_R;
    int n0 = blockIdx.x * NODES_PER_BLK;

    // ---- one-time loads ----
    for (int i = tid; i < 64 * 128; i += NTHREADS) {
        int k = i >> 7, j = i & 127;
        sW1[i] = (j < 64) ? Lz[(64 + k) * 64 + j] : Lr[(64 + k) * 64 + (j - 64)];
    }
    for (int i = tid; i < 64 * 64; i += NTHREADS)
        sW2[i] = Lh[(64 + (i >> 6)) * 64 + (i & 63)];
    for (int i = tid; i < 64 * 16; i += NTHREADS) sLin[i] = lw[i];
    for (int i = tid; i < 384; i += NTHREADS) sM[i] = g_M[i];
    for (int i = tid; i < 192; i += NTHREADS) sGb[i] = g_gb[i];
    if (tid < 16) sLb[tid] = lb[tid];
    for (int i = tid; i < NODES_PER_BLK * 96; i += NTHREADS) {
        int nn = i / 96, c = i % 96;
        int n = n0 + nn;
        sAx[i] = (n < N_NODES) ? g_ax[(size_t)n * NC + c] : 0.f;
    }
    for (int i = tid; i < 64 * LDT; i += NTHREADS) sHT[i] = 0.f;  // H0 = 0
    __syncthreads();

    int tx = tid & 15, ty = tid >> 4;     // ty 0..33
    int rbase = ty * 8;                    // 8 rows per thread (4 pairs)
    int cz = tx * 4;                       // 4 gate columns per thread

    for (int t = 0; t < TT; t++) {
        // hoist x-path values for this thread's 8 rows (read once per step)
        float axv[8][2];
#pragma unroll
        for (int i = 0; i < 8; i++) {
            int r = rbase + i;
            int nn = r >> 2, b = r & 3;
            axv[i][0] = sAx[nn * 96 + (b * 2 + 0) * TT + t];
            axv[i][1] = sAx[nn * 96 + (b * 2 + 1) * TT + t];
        }

        // =========== pass R: accR = [ax,H] @ Lr ; sHrT = H .* sigmoid(accR) ===========
        {
            u64t accR[4][4];
#pragma unroll
            for (int p = 0; p < 4; p++)
#pragma unroll
                for (int c = 0; c < 4; c++) {
                    int j = cz + c;
                    float lo = sGb[64 + j] + axv[2*p][0]   * sM[128 + j] + axv[2*p][1]   * sM[192 + j];
                    float hi = sGb[64 + j] + axv[2*p+1][0] * sM[128 + j] + axv[2*p+1][1] * sM[192 + j];
                    accR[p][c] = pk2(lo, hi);
                }
#pragma unroll 4
            for (int k = 0; k < 64; k++) {
                const u64t* ap = (const u64t*)(sHT + k * LDT + rbase);
                u64t a0 = ap[0], a1 = ap[1], a2 = ap[2], a3 = ap[3];
#pragma unroll
                for (int c = 0; c < 4; c++) {
                    u64t b = dup2(sW1[k * 128 + 64 + cz + c]);
                    fma2(accR[0][c], a0, b); fma2(accR[1][c], a1, b);
                    fma2(accR[2][c], a2, b); fma2(accR[3][c], a3, b);
                }
            }
#pragma unroll
            for (int p = 0; p < 4; p++)
#pragma unroll
                for (int c = 0; c < 4; c++) {
                    float lo, hi; up2(lo, hi, accR[p][c]);
                    int i0 = (cz + c) * LDT + rbase + 2 * p;
                    float h0, h1; up2(h0, h1, *(const u64t*)(sHT + i0));
                    *(u64t*)(sHrT + i0) = pk2(h0 * fast_sigmoid(lo), h1 * fast_sigmoid(hi));
                }
        }

        // =========== pass Z (reads sHT only; before sync to overlap) ===========
        u64t zpk[4][4];
        {
#pragma unroll
            for (int p = 0; p < 4; p++)
#pragma unroll
                for (int c = 0; c < 4; c++) {
                    int j = cz + c;
                    float lo = sGb[j] + axv[2*p][0]   * sM[j] + axv[2*p][1]   * sM[64 + j];
                    float hi = sGb[j] + axv[2*p+1][0] * sM[j] + axv[2*p+1][1] * sM[64 + j];
                    zpk[p][c] = pk2(lo, hi);
                }
#pragma unroll 4
            for (int k = 0; k < 64; k++) {
                const u64t* ap = (const u64t*)(sHT + k * LDT + rbase);
                u64t a0 = ap[0], a1 = ap[1], a2 = ap[2], a3 = ap[3];
#pragma unroll
                for (int c = 0; c < 4; c++) {
                    u64t b = dup2(sW1[k * 128 + cz + c]);
                    fma2(zpk[0][c], a0, b); fma2(zpk[1][c], a1, b);
                    fma2(zpk[2][c], a2, b); fma2(zpk[3][c], a3, b);
                }
            }
#pragma unroll
            for (int p = 0; p < 4; p++)
#pragma unroll
                for (int c = 0; c < 4; c++) {
                    float lo, hi; up2(lo, hi, zpk[p][c]);
                    zpk[p][c] = pk2(fast_sigmoid(lo), fast_sigmoid(hi));
                }
        }
        __syncthreads();   // sHrT fully written; all sHT reads of R/Z done

        // =========== pass H: candidate = [ax, H.*R] @ Lh ===========
        u64t accH[4][4];
        {
#pragma unroll
            for (int p = 0; p < 4; p++)
#pragma unroll
                for (int c = 0; c < 4; c++) {
                    int j = cz + c;
                    float lo = sGb[128 + j] + axv[2*p][0]   * sM[256 + j] + axv[2*p][1]   * sM[320 + j];
                    float hi = sGb[128 + j] + axv[2*p+1][0] * sM[256 + j] + axv[2*p+1][1] * sM[320 + j];
                    accH[p][c] = pk2(lo, hi);
                }
#pragma unroll 4
            for (int k = 0; k < 64; k++) {
                const u64t* ap = (const u64t*)(sHrT + k * LDT + rbase);
                u64t a0 = ap[0], a1 = ap[1], a2 = ap[2], a3 = ap[3];
#pragma unroll
                for (int c = 0; c < 4; c++) {
                    u64t b = dup2(sW2[k * 64 + cz + c]);
                    fma2(accH[0][c], a0, b); fma2(accH[1][c], a1, b);
                    fma2(accH[2][c], a2, b); fma2(accH[3][c], a3, b);
                }
            }
        }
        __syncthreads();   // all sHrT reads complete before overwrite

        // =========== update: Hn -> sHT ; relu(Hn) -> sHrT ===========
#pragma unroll
        for (int p = 0; p < 4; p++)
#pragma unroll
            for (int c = 0; c < 4; c++) {
                float z0, z1, hl, hh;
                up2(z0, z1, zpk[p][c]);
                up2(hl, hh, accH[p][c]);
                int i0 = (cz + c) * LDT + rbase + 2 * p;
                float h0, h1; up2(h0, h1, *(const u64t*)(sHT + i0));
                float t0 = fast_tanh(hl), t1 = fast_tanh(hh);
                float hn0 = z0 * h0 + (1.f - z0) * t0;
                float hn1 = z1 * h1 + (1.f - z1) * t1;
                *(u64t*)(sHT + i0) = pk2(hn0, hn1);
                *(u64t*)(sHrT + i0) = pk2(fmaxf(hn0, 0.f), fmaxf(hn1, 0.f));
            }
        __syncthreads();

        // =========== GEMM3: out = relu(Hn) @ lin_w + lin_b (2 threads/row, 8 outs) ===========
        {
            int r3 = tid >> 1;              // 0..271
            int o0 = (tid & 1) * 8;         // 0 or 8
            u64t acc4[4];
#pragma unroll
            for (int q = 0; q < 4; q++) acc4[q] = pk2(sLb[o0 + 2*q], sLb[o0 + 2*q + 1]);
#pragma unroll 4
            for (int k = 0; k < 64; k++) {
                u64t a = dup2(sHrT[k * LDT + r3]);
                const u64t* bp = (const u64t*)(sLin + k * 16 + o0);
                fma2(acc4[0], a, bp[0]); fma2(acc4[1], a, bp[1]);
                fma2(acc4[2], a, bp[2]); fma2(acc4[3], a, bp[3]);
            }
            int row = row0 + r3;
            if (row < NB) {
                int n = row >> 2, b = row & 3;
                float4* op = (float4*)(out + ((((size_t)b * TT + t) * N_NODES + n) * OUTD + o0));
#pragma unroll
                for (int q = 0; q < 2; q++) {
                    float x0, x1, x2, x3;
                    up2(x0, x1, acc4[2*q]);
                    up2(x2, x3, acc4[2*q + 1]);
                    op[q] = make_float4(x0, x1, x2, x3);
                }
            }
        }
        __syncthreads();   // GEMM3 reads of sHrT done before next pass R writes
    }
}

// ---------------- launch ----------------
extern "C" void kernel_launch(void* const* d_in, const int* in_sizes, int n_in,
                              void* d_out, int out_size) {
    const float* x   = (const float*)d_in[0];
    const int*   ei  = (const int*)d_in[1];
    const float* ew  = (const float*)d_in[2];
    const float* Wz  = (const float*)d_in[3];
    const float* bz  = (const float*)d_in[4];
    const float* Wr  = (const float*)d_in[5];
    const float* br  = (const float*)d_in[6];
    const float* Wh  = (const float*)d_in[7];
    const float* bh  = (const float*)d_in[8];
    const float* Lz  = (const float*)d_in[9];
    const float* Lzb = (const float*)d_in[10];
    const float* Lr  = (const float*)d_in[11];
    const float* Lrb = (const float*)d_in[12];
    const float* Lh  = (const float*)d_in[13];
    const float* Lhb = (const float*)d_in[14];
    const float* lw  = (const float*)d_in[15];
    const float* lb  = (const float*)d_in[16];
    float* out = (float*)d_out;

    int E = in_sizes[2];
    if (E > N_EDGES_MAX) E = N_EDGES_MAX;

    const int smem_bytes = SMEM_FLOATS * (int)sizeof(float);
    cudaFuncSetAttribute(k_steps, cudaFuncAttributeMaxDynamicSharedMemorySize, smem_bytes);

    // 6 launches; ncu (-s 5 -c 1) should capture launch #6 = k_steps
    k_xT_zero<<<(N_NODES * NC + 255) / 256, 256>>>(x);
    k_edge<<<(E + 255) / 256, 256>>>(ei, ew, E);
    k_scan_dinv<<<1, 1024>>>();
    k_scatter<<<(E + 255) / 256, 256>>>(ei, ew, E);
    k_agg_fold<<<(N_NODES + 7) / 8 + 1, 256>>>(Wz, bz, Wr, br, Wh, bh,
                                               Lz, Lzb, Lr, Lrb, Lh, Lhb);
    k_steps<<<GRID_STEPS, NTHREADS, smem_bytes>>>(Lz, Lr, Lh, lw, lb, out);
}